// round 16
// baseline (speedup 1.0000x reference)
#include <cuda_runtime.h>
#include <math.h>
#include <stdint.h>

#define DIM     768
#define NHEADS  12
#define HD      64
#define BATCH   8
#define SEQ     1024
#define MROWS   (BATCH*SEQ)     /* 8192 */
#define QKVN    (3*DIM)         /* 2304 */
#define SC2     0.1803368801111244f   /* 64^-0.5 * log2(e) */
#define GK      768
#define NCHUNK  24

// Scratch (allocation-free rule: __device__ globals)
__device__ __align__(1024) uint32_t g_kvf[(size_t)BATCH * NHEADS * 16 * 4096];
__device__ __align__(1024) uint32_t g_qf [(size_t)BATCH * NHEADS * 8 * 4096];
__device__ __align__(1024) uint32_t g_xf [(size_t)64 * NCHUNK * 2048];
__device__ __align__(1024) uint32_t g_af2[(size_t)64 * NCHUNK * 2048];
__device__ __align__(1024) uint32_t g_wqf[(size_t)18 * NCHUNK * 2048];
__device__ __align__(1024) uint32_t g_wpf[(size_t) 6 * NCHUNK * 2048];

__device__ __forceinline__ uint32_t smem_u32(const void* p) {
    uint32_t a;
    asm("{ .reg .u64 t; cvta.to.shared.u64 t, %1; cvt.u32.u64 %0, t; }"
        : "=r"(a) : "l"(p));
    return a;
}
__device__ __forceinline__ uint32_t pack_h2(float hi, float lo) {
    uint32_t r;
    asm("cvt.rn.f16x2.f32 %0, %1, %2;" : "=r"(r) : "f"(hi), "f"(lo));
    return r;
}
__device__ __forceinline__ float ex2(float x) {
    float r;
    asm("ex2.approx.ftz.f32 %0, %1;" : "=f"(r) : "f"(x));
    return r;
}
__device__ __forceinline__ void mma_f16(float* c, const uint32_t* a,
                                        const uint32_t* b) {
    asm volatile(
        "mma.sync.aligned.m16n8k16.row.col.f32.f16.f16.f32 "
        "{%0,%1,%2,%3}, {%4,%5,%6,%7}, {%8,%9}, {%0,%1,%2,%3};"
        : "+f"(c[0]), "+f"(c[1]), "+f"(c[2]), "+f"(c[3])
        : "r"(a[0]), "r"(a[1]), "r"(a[2]), "r"(a[3]), "r"(b[0]), "r"(b[1]));
}
__device__ __forceinline__ void cp_async16(uint32_t dst, const void* src) {
    asm volatile("cp.async.cg.shared.global [%0], [%1], 16;"
                 :: "r"(dst), "l"(src) : "memory");
}

// ===========================================================================
// conv_all: one launch converts x (A-frags), Wqkv and Wproj (B-frags).
// ===========================================================================
__global__ __launch_bounds__(256)
void conv_all(const float* __restrict__ x,
              const float* __restrict__ wq,
              const float* __restrict__ wp)
{
    const int bx = blockIdx.x;
    if (bx < 64) {
        const float* Ab = x + (size_t)bx * 128 * GK;
        uint32_t* o = g_xf + (size_t)bx * NCHUNK * 2048;
        #pragma unroll
        for (int i = 0; i < 12; i++) {
            int idx = threadIdx.x + (blockIdx.y * 12 + i) * 256;
            int row = idx / 192;
            int col = (idx % 192) * 4;
            int chunk = col >> 5, c0 = col & 31;
            float4 v = *(const float4*)(Ab + (size_t)row * GK + col);
            int k16s = c0 >> 4, klo = c0 & 15;
            int mt = row >> 4;
            uint32_t reg  = (uint32_t)(((klo >= 8) ? 2 : 0)
                           + (((row & 15) >= 8) ? 1 : 0));
            uint32_t lane = (uint32_t)((row & 7) * 4 + ((klo & 7) >> 1));
            uint32_t* oc = o + (size_t)chunk * 2048 + (k16s * 8 + mt) * 128;
            oc[lane * 4 + reg]       = pack_h2(v.y, v.x);
            oc[(lane + 1) * 4 + reg] = pack_h2(v.w, v.z);
        }
    } else {
        const bool is_q = (bx < 82);
        const int cb = is_q ? (bx - 64) : (bx - 82);
        const int N  = is_q ? QKVN : DIM;
        const float* W = is_q ? wq : wp;
        uint32_t* o = (is_q ? g_wqf : g_wpf) + (size_t)cb * NCHUNK * 2048;
        const int bn = cb * 128;
        #pragma unroll
        for (int i = 0; i < 12; i++) {
            int idx = threadIdx.x + (blockIdx.y * 12 + i) * 256;
            int n  = idx & 127;
            int k0 = (idx >> 7) * 4;
            const float* p = W + (size_t)k0 * N + bn + n;
            float v0 = p[0], v1 = p[N], v2 = p[2 * (size_t)N], v3 = p[3 * (size_t)N];
            int chunk = k0 >> 5, kl0 = k0 & 31;
            int k16s = kl0 >> 4, klo = kl0 & 15;
            int nt = n >> 3, n8 = n & 7;
            uint32_t reg  = (klo >= 8) ? 1u : 0u;
            uint32_t lane = (uint32_t)(n8 * 4 + ((klo & 7) >> 1));
            uint32_t* oc = o + (size_t)chunk * 2048 + (k16s * 16 + nt) * 64;
            oc[lane * 2 + reg]       = pack_h2(v1, v0);
            oc[(lane + 1) * 2 + reg] = pack_h2(v3, v2);
        }
    }
}

// ===========================================================================
// gemm2: fp16 m16n8k16 GEMM, 128x128 block (QKV only, mode-1 epilogue:
// acc staged to smem as f16x2 then scattered to attention-native fragments).
// ===========================================================================
__global__ __launch_bounds__(128, 2)
void gemm2(const uint32_t* __restrict__ Af, const uint32_t* __restrict__ Bf,
           const float* __restrict__ bias)
{
    extern __shared__ uint32_t sm2[];
    const uint32_t sbase = smem_u32(sm2);
    const int tid  = threadIdx.x;
    const int lane = tid & 31, wid = tid >> 5;
    const int wm   = wid >> 1, wn = wid & 1;
    const int bm   = blockIdx.y * 128, bn = blockIdx.x * 128;

    const uint4* Ab = (const uint4*)(Af + (size_t)blockIdx.y * NCHUNK * 2048);
    const uint4* Bb = (const uint4*)(Bf + (size_t)blockIdx.x * NCHUNK * 2048);

    float acc[4][8][4];
    #pragma unroll
    for (int mi = 0; mi < 4; mi++)
        #pragma unroll
        for (int ni = 0; ni < 8; ni++)
            #pragma unroll
            for (int r = 0; r < 4; r++) acc[mi][ni][r] = 0.f;

    #define COPYC(c, s)                                                       \
        do {                                                                  \
            const uint32_t dA = sbase + (uint32_t)(s) * 16384u;               \
            const uint32_t dB = dA + 8192u;                                   \
            const uint4* sa  = Ab + (c) * 512;                                \
            const uint4* sbp = Bb + (c) * 512;                                \
            _Pragma("unroll")                                                 \
            for (int i = 0; i < 4; i++) {                                     \
                int idx = tid + i * 128;                                      \
                cp_async16(dA + (uint32_t)idx * 16u, sa + idx);               \
                cp_async16(dB + (uint32_t)idx * 16u, sbp + idx);              \
            }                                                                 \
            asm volatile("cp.async.commit_group;" ::: "memory");              \
        } while (0)

    COPYC(0, 0);
    COPYC(1, 1);

    for (int c = 0; c < NCHUNK; c++) {
        if (c + 1 < NCHUNK) {
            asm volatile("cp.async.wait_group 1;" ::: "memory");
        } else {
            asm volatile("cp.async.wait_group 0;" ::: "memory");
        }
        __syncthreads();

        if (c + 2 < NCHUNK) COPYC(c + 2, (c + 2) % 3);

        const uint32_t sA = sbase + (uint32_t)(c % 3) * 16384u;
        const uint32_t sB = sA + 8192u;
        #pragma unroll
        for (int ks = 0; ks < 2; ks++) {
            uint32_t af[4][4], bf[8][2];
            #pragma unroll
            for (int mi = 0; mi < 4; mi++) {
                uint32_t off = (uint32_t)(((ks * 8 + wm * 4 + mi) << 9)
                             + (lane << 4));
                asm volatile("ld.shared.v4.b32 {%0,%1,%2,%3}, [%4];"
                             : "=r"(af[mi][0]), "=r"(af[mi][1]),
                               "=r"(af[mi][2]), "=r"(af[mi][3])
                             : "r"(sA + off));
            }
            #pragma unroll
            for (int ni = 0; ni < 8; ni++) {
                uint32_t off = (uint32_t)(((ks * 16 + wn * 8 + ni) << 8)
                             + (lane << 3));
                asm volatile("ld.shared.v2.b32 {%0,%1}, [%2];"
                             : "=r"(bf[ni][0]), "=r"(bf[ni][1])
                             : "r"(sB + off));
            }
            #pragma unroll
            for (int mi = 0; mi < 4; mi++)
                #pragma unroll
                for (int ni = 0; ni < 8; ni++)
                    mma_f16(acc[mi][ni], af[mi], bf[ni]);
        }
    }

    // ======== stage acc (bias+scale) as f16x2 into smem ========
    __syncthreads();
    const float scale = (bn < 768) ? SC2 : 1.0f;
    #pragma unroll
    for (int mi = 0; mi < 4; mi++) {
        int rl = wm * 64 + mi * 16 + (lane >> 2);
        #pragma unroll
        for (int ni = 0; ni < 8; ni++) {
            int colw = wn * 32 + ni * 4 + (lane & 3);
            float2 bb = *(const float2*)&bias[bn + colw * 2];
            sm2[rl * 65 + colw] =
                pack_h2((acc[mi][ni][1] + bb.y) * scale,
                        (acc[mi][ni][0] + bb.x) * scale);
            sm2[(rl + 8) * 65 + colw] =
                pack_h2((acc[mi][ni][3] + bb.y) * scale,
                        (acc[mi][ni][2] + bb.x) * scale);
        }
    }
    __syncthreads();

    if (bn < 768) {
        #pragma unroll 4
        for (int i = 0; i < 64; i++) {
            int idx = i * 128 + tid;
            int rl = idx >> 6, dw = idx & 63;
            uint32_t wv = sm2[rl * 65 + dw];
            int row0 = bm + rl, gcol = bn + dw * 2;
            int b = row0 >> 10, qt = (row0 >> 7) & 7;
            int rloc = row0 & 127, mt = rloc >> 4;
            int h = gcol >> 6, d = gcol & 63;
            int k16s = d >> 4, klo = d & 15;
            uint32_t lp = (uint32_t)((rloc & 7) * 4 + ((klo & 7) >> 1));
            uint32_t rg = ((klo >= 8) ? 2u : 0u) + (((rloc & 15) >= 8) ? 1u : 0u);
            g_qf[((size_t)(b * NHEADS + h) * 8 + qt) * 4096
                 + (k16s * 8 + mt) * 128 + lp * 4 + rg] = wv;
        }
    } else if (bn < 1536) {
        #pragma unroll 4
        for (int i = 0; i < 64; i++) {
            int idx = i * 128 + tid;
            int rl = idx >> 6, dw = idx & 63;
            uint32_t wv = sm2[rl * 65 + dw];
            int row0 = bm + rl;
            int b = row0 >> 10, kt = (row0 >> 6) & 15, r = row0 & 63;
            int kc = bn + dw * 2 - 768;
            int h = kc >> 6, d = kc & 63;
            int k16s = d >> 4, klo = d & 15;
            uint32_t lp = (uint32_t)((r & 7) * 4 + ((klo & 7) >> 1));
            uint32_t rg = (klo >= 8) ? 1u : 0u;
            g_kvf[((size_t)(b * NHEADS + h) * 16 + kt) * 4096
                  + ((r >> 3) * 4 + k16s) * 64 + lp * 2 + rg] = wv;
        }
    } else {
        #pragma unroll 4
        for (int i = 0; i < 32; i++) {
            int idx = i * 128 + tid;
            int rh = idx >> 6, dw = idx & 63;
            int r2 = rh * 2;
            uint32_t w0 = sm2[r2 * 65 + dw];
            uint32_t w1 = sm2[(r2 + 1) * 65 + dw];
            uint32_t lo = __byte_perm(w0, w1, 0x5410);
            uint32_t hi = __byte_perm(w0, w1, 0x7632);
            int row0 = bm + r2;
            int b = row0 >> 10, kt = (row0 >> 6) & 15, r = row0 & 63;
            int k16s = r >> 4;
            uint32_t rg = ((r & 15) >= 8) ? 1u : 0u;
            uint32_t lpk = (uint32_t)((r & 7) >> 1);
            #pragma unroll
            for (int e = 0; e < 2; e++) {
                int vcol = bn + dw * 2 + e - 1536;
                int h = vcol >> 6, dd = vcol & 63;
                uint32_t lp = (uint32_t)((dd & 7) * 4) + lpk;
                g_kvf[((size_t)(b * NHEADS + h) * 16 + kt) * 4096 + 2048
                      + ((dd >> 3) * 4 + k16s) * 64 + lp * 2 + rg]
                    = e ? hi : lo;
            }
        }
    }
    #undef COPYC
}

// ===========================================================================
// gemm3: projection GEMM, 64x128 block (grid 6 x 128), 4 warps (2m x 2n),
// 32x64 warp tile, 3-stage cp.async pipeline (12 KB/stage), 3 CTAs/SM.
// A = g_af2 (64-row half of a 128-row fragment block); C = f32 out + bias.
// ===========================================================================
__global__ __launch_bounds__(128, 3)
void gemm3(const uint32_t* __restrict__ Af, const uint32_t* __restrict__ Bf,
           const float* __restrict__ bias, float* __restrict__ C, int N)
{
    extern __shared__ uint32_t sm3[];
    const uint32_t sbase = smem_u32(sm3);
    const int tid  = threadIdx.x;
    const int lane = tid & 31, wid = tid >> 5;
    const int wm   = wid >> 1, wn = wid & 1;
    const int bm   = blockIdx.y * 64, bn = blockIdx.x * 128;
    const int mhalf = blockIdx.y & 1;

    const uint4* Ab = (const uint4*)(Af + (size_t)(blockIdx.y >> 1) * NCHUNK * 2048);
    const uint4* Bb = (const uint4*)(Bf + (size_t)blockIdx.x * NCHUNK * 2048);

    float acc[2][8][4];
    #pragma unroll
    for (int mi = 0; mi < 2; mi++)
        #pragma unroll
        for (int ni = 0; ni < 8; ni++)
            #pragma unroll
            for (int r = 0; r < 4; r++) acc[mi][ni][r] = 0.f;

    // stage = A 4KB (1024 words: [k16s*4+mtl]*128) | B 8KB
    #define COPYD(c, s)                                                       \
        do {                                                                  \
            const uint32_t dA = sbase + (uint32_t)(s) * 12288u;               \
            const uint32_t dB = dA + 4096u;                                   \
            _Pragma("unroll")                                                 \
            for (int j = 0; j < 2; j++) {                                     \
                int idx = j * 128 + tid;                                      \
                const uint4* src = Ab + (c) * 512 + j * 256                   \
                                 + mhalf * 128 + (idx & 127);                 \
                cp_async16(dA + (uint32_t)idx * 16u, src);                    \
            }                                                                 \
            const uint4* sbp = Bb + (c) * 512;                                \
            _Pragma("unroll")                                                 \
            for (int j = 0; j < 4; j++) {                                     \
                int idx = j * 128 + tid;                                      \
                cp_async16(dB + (uint32_t)idx * 16u, sbp + idx);              \
            }                                                                 \
            asm volatile("cp.async.commit_group;" ::: "memory");              \
        } while (0)

    COPYD(0, 0);
    COPYD(1, 1);

    for (int c = 0; c < NCHUNK; c++) {
        if (c + 1 < NCHUNK) {
            asm volatile("cp.async.wait_group 1;" ::: "memory");
        } else {
            asm volatile("cp.async.wait_group 0;" ::: "memory");
        }
        __syncthreads();

        if (c + 2 < NCHUNK) COPYD(c + 2, (c + 2) % 3);

        const uint32_t sA = sbase + (uint32_t)(c % 3) * 12288u;
        const uint32_t sB = sA + 4096u;
        #pragma unroll
        for (int ks = 0; ks < 2; ks++) {
            uint32_t af[2][4], bf[8][2];
            #pragma unroll
            for (int mi = 0; mi < 2; mi++) {
                uint32_t off = (uint32_t)(((ks * 4 + wm * 2 + mi) << 9)
                             + (lane << 4));
                asm volatile("ld.shared.v4.b32 {%0,%1,%2,%3}, [%4];"
                             : "=r"(af[mi][0]), "=r"(af[mi][1]),
                               "=r"(af[mi][2]), "=r"(af[mi][3])
                             : "r"(sA + off));
            }
            #pragma unroll
            for (int ni = 0; ni < 8; ni++) {
                uint32_t off = (uint32_t)(((ks * 16 + wn * 8 + ni) << 8)
                             + (lane << 3));
                asm volatile("ld.shared.v2.b32 {%0,%1}, [%2];"
                             : "=r"(bf[ni][0]), "=r"(bf[ni][1])
                             : "r"(sB + off));
            }
            #pragma unroll
            for (int mi = 0; mi < 2; mi++)
                #pragma unroll
                for (int ni = 0; ni < 8; ni++)
                    mma_f16(acc[mi][ni], af[mi], bf[ni]);
        }
    }

    #pragma unroll
    for (int mi = 0; mi < 2; mi++) {
        int row = bm + wm * 32 + mi * 16 + (lane >> 2);
        #pragma unroll
        for (int ni = 0; ni < 8; ni++) {
            int col = bn + wn * 64 + ni * 8 + (lane & 3) * 2;
            float2 bb = *(const float2*)&bias[col];
            float2 o0, o1;
            o0.x = acc[mi][ni][0] + bb.x;
            o0.y = acc[mi][ni][1] + bb.y;
            o1.x = acc[mi][ni][2] + bb.x;
            o1.y = acc[mi][ni][3] + bb.y;
            *(float2*)&C[(size_t)row * N + col]       = o0;
            *(float2*)&C[(size_t)(row + 8) * N + col] = o1;
        }
    }
    #undef COPYD
}

// ===========================================================================
// fp16 flash attention (round-14/15 validated + alpha-skip).
// CTA = (b,h,128q), 4 warps, 32 q-rows/warp.
// ===========================================================================
__global__ __launch_bounds__(128, 2)
void attn_mma()
{
    extern __shared__ uint32_t smu[];
    const uint32_t sb  = smem_u32(smu);
    const uint32_t VsB = sb + 16384u;
    const uint32_t PsB = sb + 24576u;

    const int tid  = threadIdx.x;
    const int lane = tid & 31, w = tid >> 5;
    const int bh   = blockIdx.y;
    const int b    = bh / NHEADS;
    const int h    = bh % NHEADS;

    uint32_t qa[4][8];
    {
        const uint32_t* qbase = g_qf + ((size_t)bh * 8 + blockIdx.x) * 4096;
        #pragma unroll
        for (int ks = 0; ks < 4; ks++)
            #pragma unroll
            for (int hf = 0; hf < 2; hf++) {
                uint4 t = *(const uint4*)(qbase + (ks * 8 + w * 2 + hf) * 128
                                          + lane * 4);
                qa[ks][hf * 4 + 0] = t.x;
                qa[ks][hf * 4 + 1] = t.y;
                qa[ks][hf * 4 + 2] = t.z;
                qa[ks][hf * 4 + 3] = t.w;
            }
    }

    float oacc[2][8][4];
    #pragma unroll
    for (int hf = 0; hf < 2; hf++)
        #pragma unroll
        for (int nt = 0; nt < 8; nt++)
            #pragma unroll
            for (int r = 0; r < 4; r++) oacc[hf][nt][r] = 0.f;
    float m[4] = {-INFINITY, -INFINITY, -INFINITY, -INFINITY};
    float l[4] = {0.f, 0.f, 0.f, 0.f};

    const uint32_t Pwarp = PsB + (uint32_t)w * 4096u;
    const uint4* kvsrc = (const uint4*)(g_kvf + (size_t)bh * 16 * 4096);

    {
        #pragma unroll
        for (int i = 0; i < 4; i++) {
            int idx = i * 128 + tid;
            cp_async16(sb + (uint32_t)idx * 16u, kvsrc + idx);
        }
        asm volatile("cp.async.commit_group;" ::: "memory");
    }

    for (int kt = 0; kt < SEQ / 64; kt++) {
        asm volatile("cp.async.wait_group 0;" ::: "memory");
        __syncthreads();

        {
            const uint4* src = kvsrc + (size_t)kt * 1024 + 512;
            #pragma unroll
            for (int i = 0; i < 4; i++) {
                int idx = i * 128 + tid;
                cp_async16(VsB + (uint32_t)idx * 16u, src + idx);
            }
            asm volatile("cp.async.commit_group;" ::: "memory");
        }
        if (kt + 1 < SEQ / 64) {
            const uint4* src = kvsrc + (size_t)(kt + 1) * 1024;
            const uint32_t dst = sb + (uint32_t)((kt + 1) & 1) * 8192u;
            #pragma unroll
            for (int i = 0; i < 4; i++) {
                int idx = i * 128 + tid;
                cp_async16(dst + (uint32_t)idx * 16u, src + idx);
            }
            asm volatile("cp.async.commit_group;" ::: "memory");
        }

        const uint32_t KsB = sb + (uint32_t)(kt & 1) * 8192u;

        float sacc[2][8][4];
        #pragma unroll
        for (int hf = 0; hf < 2; hf++)
            #pragma unroll
            for (int nt = 0; nt < 8; nt++)
                #pragma unroll
                for (int r = 0; r < 4; r++) sacc[hf][nt][r] = 0.f;

        #pragma unroll
        for (int ks = 0; ks < 4; ks++) {
            uint32_t bf[8][2];
            #pragma unroll
            for (int nt = 0; nt < 8; nt++) {
                uint32_t off = (uint32_t)((nt * 4 + ks) << 8) + (lane << 3);
                asm volatile("ld.shared.v2.b32 {%0,%1}, [%2];"
                             : "=r"(bf[nt][0]), "=r"(bf[nt][1])
                             : "r"(KsB + off));
            }
            #pragma unroll
            for (int nt = 0; nt < 8; nt++) {
                mma_f16(sacc[0][nt], qa[ks],     bf[nt]);
                mma_f16(sacc[1][nt], qa[ks] + 4, bf[nt]);
            }
        }

        if (kt + 1 < SEQ / 64) {
            asm volatile("cp.async.wait_group 1;" ::: "memory");
        } else {
            asm volatile("cp.async.wait_group 0;" ::: "memory");
        }
        __syncthreads();

        float mx[4] = {-INFINITY, -INFINITY, -INFINITY, -INFINITY};
        #pragma unroll
        for (int hf = 0; hf < 2; hf++)
            #pragma unroll
            for (int nt = 0; nt < 8; nt++) {
                mx[hf * 2]     = fmaxf(mx[hf * 2],
                                       fmaxf(sacc[hf][nt][0], sacc[hf][nt][1]));
                mx[hf * 2 + 1] = fmaxf(mx[hf * 2 + 1],
                                       fmaxf(sacc[hf][nt][2], sacc[hf][nt][3]));
            }
        float av[4];
        #pragma unroll
        for (int j = 0; j < 4; j++) {
            mx[j] = fmaxf(mx[j], __shfl_xor_sync(0xffffffffu, mx[j], 1));
            mx[j] = fmaxf(mx[j], __shfl_xor_sync(0xffffffffu, mx[j], 2));
            float mn = fmaxf(m[j], mx[j]);
            av[j] = ex2(m[j] - mn);
            m[j] = mn;
            l[j] *= av[j];
        }

        // alpha-skip: rescale oacc only if any alpha != 1 (bit-exact: *1.0)
        bool need = (av[0] != 1.f) | (av[1] != 1.f)
                  | (av[2] != 1.f) | (av[3] != 1.f);
        if (__any_sync(0xffffffffu, need)) {
            #pragma unroll
            for (int hf = 0; hf < 2; hf++)
                #pragma unroll
                for (int nt = 0; nt < 8; nt++) {
                    oacc[hf][nt][0] *= av[hf * 2];
                    oacc[hf][nt][1] *= av[hf * 2];
                    oacc[hf][nt][2] *= av[hf * 2 + 1];
                    oacc[hf][nt][3] *= av[hf * 2 + 1];
                }
        }

        float sum[4] = {0.f, 0.f, 0.f, 0.f};
        #pragma unroll
        for (int hf = 0; hf < 2; hf++) {
            #pragma unroll
            for (int nt = 0; nt < 8; nt++) {
                float p00 = ex2(sacc[hf][nt][0] - m[hf * 2]);
                float p01 = ex2(sacc[hf][nt][1] - m[hf * 2]);
                float p10 = ex2(sacc[hf][nt][2] - m[hf * 2 + 1]);
                float p11 = ex2(sacc[hf][nt][3] - m[hf * 2 + 1]);
                sum[hf * 2]     += p00 + p01;
                sum[hf * 2 + 1] += p10 + p11;
                uint32_t baddr = Pwarp + (uint32_t)(hf * 2048)
                               + (uint32_t)((nt >> 1) * 512)
                               + (uint32_t)(lane << 4) + (uint32_t)((nt & 1) * 8);
                asm volatile("st.shared.b32 [%0], %1;"
                             :: "r"(baddr),     "r"(pack_h2(p01, p00)) : "memory");
                asm volatile("st.shared.b32 [%0], %1;"
                             :: "r"(baddr + 4), "r"(pack_h2(p11, p10)) : "memory");
            }
        }
        #pragma unroll
        for (int j = 0; j < 4; j++) {
            sum[j] += __shfl_xor_sync(0xffffffffu, sum[j], 1);
            sum[j] += __shfl_xor_sync(0xffffffffu, sum[j], 2);
            l[j] += sum[j];
        }

        #pragma unroll
        for (int ks = 0; ks < 4; ks++) {
            uint32_t pa0[4], pa1[4];
            uint32_t pb = Pwarp + (uint32_t)(ks * 512) + (uint32_t)(lane << 4);
            asm volatile("ld.shared.v4.b32 {%0,%1,%2,%3}, [%4];"
                         : "=r"(pa0[0]), "=r"(pa0[1]), "=r"(pa0[2]), "=r"(pa0[3])
                         : "r"(pb));
            asm volatile("ld.shared.v4.b32 {%0,%1,%2,%3}, [%4];"
                         : "=r"(pa1[0]), "=r"(pa1[1]), "=r"(pa1[2]), "=r"(pa1[3])
                         : "r"(pb + 2048u));
            #pragma unroll
            for (int nt = 0; nt < 8; nt++) {
                uint32_t vb[2];
                uint32_t off = (uint32_t)((nt * 4 + ks) << 8) + (lane << 3);
                asm volatile("ld.shared.v2.b32 {%0,%1}, [%2];"
                             : "=r"(vb[0]), "=r"(vb[1]) : "r"(VsB + off));
                mma_f16(oacc[0][nt], pa0, vb);
                mma_f16(oacc[1][nt], pa1, vb);
            }
        }
    }

    {
        const int rb = b * 8 + blockIdx.x;
        #pragma unroll
        for (int hf = 0; hf < 2; hf++) {
            float inv0 = 1.f / l[hf * 2], inv1 = 1.f / l[hf * 2 + 1];
            int mt = w * 2 + hf;
            #pragma unroll
            for (int nt = 0; nt < 8; nt++) {
                int chunk = h * 2 + (nt >> 2);
                int k16s  = (nt >> 1) & 1;
                uint32_t rg = (uint32_t)((nt & 1) * 2);
                uint32_t* o = g_af2 + ((size_t)rb * NCHUNK + chunk) * 2048
                            + (k16s * 8 + mt) * 128 + lane * 4 + rg;
                o[0] = pack_h2(oacc[hf][nt][1] * inv0, oacc[hf][nt][0] * inv0);
                o[1] = pack_h2(oacc[hf][nt][3] * inv1, oacc[hf][nt][2] * inv1);
            }
        }
    }
}

// ---------------------------------------------------------------------------
extern "C" void kernel_launch(void* const* d_in, const int* in_sizes, int n_in,
                              void* d_out, int out_size)
{
    const float* x      = (const float*)d_in[0];
    const float* w_qkv  = (const float*)d_in[1];
    const float* b_qkv  = (const float*)d_in[2];
    const float* w_proj = (const float*)d_in[3];
    const float* b_proj = (const float*)d_in[4];
    float* out = (float*)d_out;

    uint32_t *xf = nullptr, *af2 = nullptr, *wqf = nullptr, *wpf = nullptr;
    cudaGetSymbolAddress((void**)&xf,  g_xf);
    cudaGetSymbolAddress((void**)&af2, g_af2);
    cudaGetSymbolAddress((void**)&wqf, g_wqf);
    cudaGetSymbolAddress((void**)&wpf, g_wpf);

    const int gemm_smem  = 49152;   // gemm2: 3 x 16 KB
    const int gemm3_smem = 36864;   // gemm3: 3 x 12 KB
    const int attn_smem  = 40960;
    cudaFuncSetAttribute(gemm2,
                         cudaFuncAttributeMaxDynamicSharedMemorySize, gemm_smem);
    cudaFuncSetAttribute(gemm3,
                         cudaFuncAttributeMaxDynamicSharedMemorySize, gemm3_smem);
    cudaFuncSetAttribute(attn_mma,
                         cudaFuncAttributeMaxDynamicSharedMemorySize, attn_smem);

    // 0) all input conversions
    conv_all<<<dim3(88, 8), 256>>>(x, w_qkv, w_proj);

    // 1) QKV projection -> Q/K/V attention-native fragments
    gemm2<<<dim3(QKVN / 128, MROWS / 128), 128, gemm_smem>>>(xf, wqf, b_qkv);

    // 2) attention -> proj A-fragments
    attn_mma<<<dim3(SEQ / 128, BATCH * NHEADS), 128, attn_smem>>>();

    // 3) output projection (64-row blocks, 3 CTAs/SM)
    gemm3<<<dim3(DIM / 128, MROWS / 64), 128, gemm3_smem>>>(
        af2, wpf, b_proj, out, DIM);
}

// round 17
// speedup vs baseline: 1.5409x; 1.5409x over previous
#include <cuda_runtime.h>
#include <math.h>
#include <stdint.h>

#define DIM     768
#define NHEADS  12
#define HD      64
#define BATCH   8
#define SEQ     1024
#define MROWS   (BATCH*SEQ)     /* 8192 */
#define QKVN    (3*DIM)         /* 2304 */
#define SC2     0.1803368801111244f   /* 64^-0.5 * log2(e) */
#define GK      768
#define NCHUNK  24

// Scratch (allocation-free rule: __device__ globals)
__device__ __align__(1024) uint32_t g_kvf[(size_t)BATCH * NHEADS * 16 * 4096];
__device__ __align__(1024) uint32_t g_qf [(size_t)BATCH * NHEADS * 8 * 4096];
__device__ __align__(1024) uint32_t g_xf [(size_t)64 * NCHUNK * 2048];
__device__ __align__(1024) uint32_t g_af2[(size_t)64 * NCHUNK * 2048];
__device__ __align__(1024) uint32_t g_wqf[(size_t)18 * NCHUNK * 2048];
__device__ __align__(1024) uint32_t g_wpf[(size_t) 6 * NCHUNK * 2048];

__device__ __forceinline__ uint32_t smem_u32(const void* p) {
    uint32_t a;
    asm("{ .reg .u64 t; cvta.to.shared.u64 t, %1; cvt.u32.u64 %0, t; }"
        : "=r"(a) : "l"(p));
    return a;
}
__device__ __forceinline__ uint32_t pack_h2(float hi, float lo) {
    uint32_t r;
    asm("cvt.rn.f16x2.f32 %0, %1, %2;" : "=r"(r) : "f"(hi), "f"(lo));
    return r;
}
__device__ __forceinline__ float ex2(float x) {
    float r;
    asm("ex2.approx.ftz.f32 %0, %1;" : "=f"(r) : "f"(x));
    return r;
}
__device__ __forceinline__ void mma_f16(float* c, const uint32_t* a,
                                        const uint32_t* b) {
    asm volatile(
        "mma.sync.aligned.m16n8k16.row.col.f32.f16.f16.f32 "
        "{%0,%1,%2,%3}, {%4,%5,%6,%7}, {%8,%9}, {%0,%1,%2,%3};"
        : "+f"(c[0]), "+f"(c[1]), "+f"(c[2]), "+f"(c[3])
        : "r"(a[0]), "r"(a[1]), "r"(a[2]), "r"(a[3]), "r"(b[0]), "r"(b[1]));
}
__device__ __forceinline__ void cp_async16(uint32_t dst, const void* src) {
    asm volatile("cp.async.cg.shared.global [%0], [%1], 16;"
                 :: "r"(dst), "l"(src) : "memory");
}

// ===========================================================================
// conv_all: one launch converts x (A-frags), Wqkv and Wproj (B-frags).
// blockIdx.x: [0,64) x | [64,82) Wqkv | [82,88) Wproj.  grid (88, 8), 256 thr.
// ===========================================================================
__global__ __launch_bounds__(256)
void conv_all(const float* __restrict__ x,
              const float* __restrict__ wq,
              const float* __restrict__ wp)
{
    const int bx = blockIdx.x;
    if (bx < 64) {
        const float* Ab = x + (size_t)bx * 128 * GK;
        uint32_t* o = g_xf + (size_t)bx * NCHUNK * 2048;
        #pragma unroll
        for (int i = 0; i < 12; i++) {
            int idx = threadIdx.x + (blockIdx.y * 12 + i) * 256;
            int row = idx / 192;
            int col = (idx % 192) * 4;
            int chunk = col >> 5, c0 = col & 31;
            float4 v = *(const float4*)(Ab + (size_t)row * GK + col);
            int k16s = c0 >> 4, klo = c0 & 15;
            int mt = row >> 4;
            uint32_t reg  = (uint32_t)(((klo >= 8) ? 2 : 0)
                           + (((row & 15) >= 8) ? 1 : 0));
            uint32_t lane = (uint32_t)((row & 7) * 4 + ((klo & 7) >> 1));
            uint32_t* oc = o + (size_t)chunk * 2048 + (k16s * 8 + mt) * 128;
            oc[lane * 4 + reg]       = pack_h2(v.y, v.x);
            oc[(lane + 1) * 4 + reg] = pack_h2(v.w, v.z);
        }
    } else {
        const bool is_q = (bx < 82);
        const int cb = is_q ? (bx - 64) : (bx - 82);
        const int N  = is_q ? QKVN : DIM;
        const float* W = is_q ? wq : wp;
        uint32_t* o = (is_q ? g_wqf : g_wpf) + (size_t)cb * NCHUNK * 2048;
        const int bn = cb * 128;
        #pragma unroll
        for (int i = 0; i < 12; i++) {
            int idx = threadIdx.x + (blockIdx.y * 12 + i) * 256;
            int n  = idx & 127;
            int k0 = (idx >> 7) * 4;
            const float* p = W + (size_t)k0 * N + bn + n;
            float v0 = p[0], v1 = p[N], v2 = p[2 * (size_t)N], v3 = p[3 * (size_t)N];
            int chunk = k0 >> 5, kl0 = k0 & 31;
            int k16s = kl0 >> 4, klo = kl0 & 15;
            int nt = n >> 3, n8 = n & 7;
            uint32_t reg  = (klo >= 8) ? 1u : 0u;
            uint32_t lane = (uint32_t)(n8 * 4 + ((klo & 7) >> 1));
            uint32_t* oc = o + (size_t)chunk * 2048 + (k16s * 16 + nt) * 64;
            oc[lane * 2 + reg]       = pack_h2(v1, v0);
            oc[(lane + 1) * 2 + reg] = pack_h2(v3, v2);
        }
    }
}

// ===========================================================================
// gemm2: fp16 m16n8k16 GEMM (validated mainloop).
// mode 0: C = A@B + bias (f32).
// mode 1: QKV — acc staged to smem as f16x2 [128][65], then low-register
//   scatter to attention-native fragments (Q A-frags | K B-frags | V^T via
//   byte_perm row-pair recombine).
// ===========================================================================
__global__ __launch_bounds__(128, 2)
void gemm2(const uint32_t* __restrict__ Af, const uint32_t* __restrict__ Bf,
           const float* __restrict__ bias, float* __restrict__ C, int N,
           int mode)
{
    extern __shared__ uint32_t sm2[];
    const uint32_t sbase = smem_u32(sm2);
    const int tid  = threadIdx.x;
    const int lane = tid & 31, wid = tid >> 5;
    const int wm   = wid >> 1, wn = wid & 1;
    const int bm   = blockIdx.y * 128, bn = blockIdx.x * 128;

    const uint4* Ab = (const uint4*)(Af + (size_t)blockIdx.y * NCHUNK * 2048);
    const uint4* Bb = (const uint4*)(Bf + (size_t)blockIdx.x * NCHUNK * 2048);

    float acc[4][8][4];
    #pragma unroll
    for (int mi = 0; mi < 4; mi++)
        #pragma unroll
        for (int ni = 0; ni < 8; ni++)
            #pragma unroll
            for (int r = 0; r < 4; r++) acc[mi][ni][r] = 0.f;

    #define COPYC(c, s)                                                       \
        do {                                                                  \
            const uint32_t dA = sbase + (uint32_t)(s) * 16384u;               \
            const uint32_t dB = dA + 8192u;                                   \
            const uint4* sa  = Ab + (c) * 512;                                \
            const uint4* sbp = Bb + (c) * 512;                                \
            _Pragma("unroll")                                                 \
            for (int i = 0; i < 4; i++) {                                     \
                int idx = tid + i * 128;                                      \
                cp_async16(dA + (uint32_t)idx * 16u, sa + idx);               \
                cp_async16(dB + (uint32_t)idx * 16u, sbp + idx);              \
            }                                                                 \
            asm volatile("cp.async.commit_group;" ::: "memory");              \
        } while (0)

    COPYC(0, 0);
    COPYC(1, 1);

    for (int c = 0; c < NCHUNK; c++) {
        if (c + 1 < NCHUNK) {
            asm volatile("cp.async.wait_group 1;" ::: "memory");
        } else {
            asm volatile("cp.async.wait_group 0;" ::: "memory");
        }
        __syncthreads();

        if (c + 2 < NCHUNK) COPYC(c + 2, (c + 2) % 3);

        const uint32_t sA = sbase + (uint32_t)(c % 3) * 16384u;
        const uint32_t sB = sA + 8192u;
        #pragma unroll
        for (int ks = 0; ks < 2; ks++) {
            uint32_t af[4][4], bf[8][2];
            #pragma unroll
            for (int mi = 0; mi < 4; mi++) {
                uint32_t off = (uint32_t)(((ks * 8 + wm * 4 + mi) << 9)
                             + (lane << 4));
                asm volatile("ld.shared.v4.b32 {%0,%1,%2,%3}, [%4];"
                             : "=r"(af[mi][0]), "=r"(af[mi][1]),
                               "=r"(af[mi][2]), "=r"(af[mi][3])
                             : "r"(sA + off));
            }
            #pragma unroll
            for (int ni = 0; ni < 8; ni++) {
                uint32_t off = (uint32_t)(((ks * 16 + wn * 8 + ni) << 8)
                             + (lane << 3));
                asm volatile("ld.shared.v2.b32 {%0,%1}, [%2];"
                             : "=r"(bf[ni][0]), "=r"(bf[ni][1])
                             : "r"(sB + off));
            }
            #pragma unroll
            for (int mi = 0; mi < 4; mi++)
                #pragma unroll
                for (int ni = 0; ni < 8; ni++)
                    mma_f16(acc[mi][ni], af[mi], bf[ni]);
        }
    }

    if (mode == 0) {
        // ---- plain f32 epilogue ----
        #pragma unroll
        for (int mi = 0; mi < 4; mi++) {
            int row = bm + wm * 64 + mi * 16 + (lane >> 2);
            #pragma unroll
            for (int ni = 0; ni < 8; ni++) {
                int col = bn + wn * 64 + ni * 8 + (lane & 3) * 2;
                float2 bb = *(const float2*)&bias[col];
                float2 o0, o1;
                o0.x = acc[mi][ni][0] + bb.x;
                o0.y = acc[mi][ni][1] + bb.y;
                o1.x = acc[mi][ni][2] + bb.x;
                o1.y = acc[mi][ni][3] + bb.y;
                *(float2*)&C[(size_t)row * N + col]       = o0;
                *(float2*)&C[(size_t)(row + 8) * N + col] = o1;
            }
        }
        return;
    }

    // ======== mode 1: stage acc (bias+scale) as f16x2 into smem ========
    __syncthreads();   // pipeline smem no longer needed
    const float scale = (bn < 768) ? SC2 : 1.0f;
    #pragma unroll
    for (int mi = 0; mi < 4; mi++) {
        int rl = wm * 64 + mi * 16 + (lane >> 2);
        #pragma unroll
        for (int ni = 0; ni < 8; ni++) {
            int colw = wn * 32 + ni * 4 + (lane & 3);   // word col (0..63)
            float2 bb = *(const float2*)&bias[bn + colw * 2];
            sm2[rl * 65 + colw] =
                pack_h2((acc[mi][ni][1] + bb.y) * scale,
                        (acc[mi][ni][0] + bb.x) * scale);
            sm2[(rl + 8) * 65 + colw] =
                pack_h2((acc[mi][ni][3] + bb.y) * scale,
                        (acc[mi][ni][2] + bb.x) * scale);
        }
    }
    __syncthreads();

    if (bn < 768) {
        // ---- Q scatter: A-fragment blocks (word = col-pair, direct) ----
        #pragma unroll 4
        for (int i = 0; i < 64; i++) {
            int idx = i * 128 + tid;
            int rl = idx >> 6, dw = idx & 63;
            uint32_t wv = sm2[rl * 65 + dw];
            int row0 = bm + rl, gcol = bn + dw * 2;
            int b = row0 >> 10, qt = (row0 >> 7) & 7;
            int rloc = row0 & 127, mt = rloc >> 4;
            int h = gcol >> 6, d = gcol & 63;
            int k16s = d >> 4, klo = d & 15;
            uint32_t lp = (uint32_t)((rloc & 7) * 4 + ((klo & 7) >> 1));
            uint32_t rg = ((klo >= 8) ? 2u : 0u) + (((rloc & 15) >= 8) ? 1u : 0u);
            g_qf[((size_t)(b * NHEADS + h) * 8 + qt) * 4096
                 + (k16s * 8 + mt) * 128 + lp * 4 + rg] = wv;
        }
    } else if (bn < 1536) {
        // ---- K scatter: B-fragment blocks (word = col-pair, direct) ----
        #pragma unroll 4
        for (int i = 0; i < 64; i++) {
            int idx = i * 128 + tid;
            int rl = idx >> 6, dw = idx & 63;
            uint32_t wv = sm2[rl * 65 + dw];
            int row0 = bm + rl;
            int b = row0 >> 10, kt = (row0 >> 6) & 15, r = row0 & 63;
            int kc = bn + dw * 2 - 768;
            int h = kc >> 6, d = kc & 63;
            int k16s = d >> 4, klo = d & 15;
            uint32_t lp = (uint32_t)((r & 7) * 4 + ((klo & 7) >> 1));
            uint32_t rg = (klo >= 8) ? 1u : 0u;
            g_kvf[((size_t)(b * NHEADS + h) * 16 + kt) * 4096
                  + ((r >> 3) * 4 + k16s) * 64 + lp * 2 + rg] = wv;
        }
    } else {
        // ---- V scatter: V^T B-frags; recombine row-pairs via byte_perm ----
        #pragma unroll 4
        for (int i = 0; i < 32; i++) {
            int idx = i * 128 + tid;           // 0..4095
            int rh = idx >> 6, dw = idx & 63;
            int r2 = rh * 2;
            uint32_t w0 = sm2[r2 * 65 + dw];
            uint32_t w1 = sm2[(r2 + 1) * 65 + dw];
            uint32_t lo = __byte_perm(w0, w1, 0x5410);
            uint32_t hi = __byte_perm(w0, w1, 0x7632);
            int row0 = bm + r2;
            int b = row0 >> 10, kt = (row0 >> 6) & 15, r = row0 & 63;
            int k16s = r >> 4;
            uint32_t rg = ((r & 15) >= 8) ? 1u : 0u;
            uint32_t lpk = (uint32_t)((r & 7) >> 1);
            #pragma unroll
            for (int e = 0; e < 2; e++) {
                int vcol = bn + dw * 2 + e - 1536;
                int h = vcol >> 6, dd = vcol & 63;
                uint32_t lp = (uint32_t)((dd & 7) * 4) + lpk;
                g_kvf[((size_t)(b * NHEADS + h) * 16 + kt) * 4096 + 2048
                      + ((dd >> 3) * 4 + k16s) * 64 + lp * 2 + rg]
                    = e ? hi : lo;
            }
        }
    }
    #undef COPYC
}

// ===========================================================================
// fp16 flash attention (round-14/15 validated): CTA = (b,h,128q), 4 warps,
// 32 q-rows/warp. Q from g_qf; output -> g_af2 A-fragment blocks.
// SMEM: K0 8K | K1 8K | V 8K | Ps 16K = 40 KB.
// ===========================================================================
__global__ __launch_bounds__(128, 2)
void attn_mma()
{
    extern __shared__ uint32_t smu[];
    const uint32_t sb  = smem_u32(smu);
    const uint32_t VsB = sb + 16384u;
    const uint32_t PsB = sb + 24576u;

    const int tid  = threadIdx.x;
    const int lane = tid & 31, w = tid >> 5;
    const int bh   = blockIdx.y;
    const int b    = bh / NHEADS;
    const int h    = bh % NHEADS;

    uint32_t qa[4][8];
    {
        const uint32_t* qbase = g_qf + ((size_t)bh * 8 + blockIdx.x) * 4096;
        #pragma unroll
        for (int ks = 0; ks < 4; ks++)
            #pragma unroll
            for (int hf = 0; hf < 2; hf++) {
                uint4 t = *(const uint4*)(qbase + (ks * 8 + w * 2 + hf) * 128
                                          + lane * 4);
                qa[ks][hf * 4 + 0] = t.x;
                qa[ks][hf * 4 + 1] = t.y;
                qa[ks][hf * 4 + 2] = t.z;
                qa[ks][hf * 4 + 3] = t.w;
            }
    }

    float oacc[2][8][4];
    #pragma unroll
    for (int hf = 0; hf < 2; hf++)
        #pragma unroll
        for (int nt = 0; nt < 8; nt++)
            #pragma unroll
            for (int r = 0; r < 4; r++) oacc[hf][nt][r] = 0.f;
    float m[4] = {-INFINITY, -INFINITY, -INFINITY, -INFINITY};
    float l[4] = {0.f, 0.f, 0.f, 0.f};

    const uint32_t Pwarp = PsB + (uint32_t)w * 4096u;
    const uint4* kvsrc = (const uint4*)(g_kvf + (size_t)bh * 16 * 4096);

    {
        #pragma unroll
        for (int i = 0; i < 4; i++) {
            int idx = i * 128 + tid;
            cp_async16(sb + (uint32_t)idx * 16u, kvsrc + idx);
        }
        asm volatile("cp.async.commit_group;" ::: "memory");
    }

    for (int kt = 0; kt < SEQ / 64; kt++) {
        asm volatile("cp.async.wait_group 0;" ::: "memory");
        __syncthreads();

        {
            const uint4* src = kvsrc + (size_t)kt * 1024 + 512;
            #pragma unroll
            for (int i = 0; i < 4; i++) {
                int idx = i * 128 + tid;
                cp_async16(VsB + (uint32_t)idx * 16u, src + idx);
            }
            asm volatile("cp.async.commit_group;" ::: "memory");
        }
        if (kt + 1 < SEQ / 64) {
            const uint4* src = kvsrc + (size_t)(kt + 1) * 1024;
            const uint32_t dst = sb + (uint32_t)((kt + 1) & 1) * 8192u;
            #pragma unroll
            for (int i = 0; i < 4; i++) {
                int idx = i * 128 + tid;
                cp_async16(dst + (uint32_t)idx * 16u, src + idx);
            }
            asm volatile("cp.async.commit_group;" ::: "memory");
        }

        const uint32_t KsB = sb + (uint32_t)(kt & 1) * 8192u;

        float sacc[2][8][4];
        #pragma unroll
        for (int hf = 0; hf < 2; hf++)
            #pragma unroll
            for (int nt = 0; nt < 8; nt++)
                #pragma unroll
                for (int r = 0; r < 4; r++) sacc[hf][nt][r] = 0.f;

        #pragma unroll
        for (int ks = 0; ks < 4; ks++) {
            uint32_t bf[8][2];
            #pragma unroll
            for (int nt = 0; nt < 8; nt++) {
                uint32_t off = (uint32_t)((nt * 4 + ks) << 8) + (lane << 3);
                asm volatile("ld.shared.v2.b32 {%0,%1}, [%2];"
                             : "=r"(bf[nt][0]), "=r"(bf[nt][1])
                             : "r"(KsB + off));
            }
            #pragma unroll
            for (int nt = 0; nt < 8; nt++) {
                mma_f16(sacc[0][nt], qa[ks],     bf[nt]);
                mma_f16(sacc[1][nt], qa[ks] + 4, bf[nt]);
            }
        }

        if (kt + 1 < SEQ / 64) {
            asm volatile("cp.async.wait_group 1;" ::: "memory");
        } else {
            asm volatile("cp.async.wait_group 0;" ::: "memory");
        }
        __syncthreads();

        float mx[4] = {-INFINITY, -INFINITY, -INFINITY, -INFINITY};
        #pragma unroll
        for (int hf = 0; hf < 2; hf++)
            #pragma unroll
            for (int nt = 0; nt < 8; nt++) {
                mx[hf * 2]     = fmaxf(mx[hf * 2],
                                       fmaxf(sacc[hf][nt][0], sacc[hf][nt][1]));
                mx[hf * 2 + 1] = fmaxf(mx[hf * 2 + 1],
                                       fmaxf(sacc[hf][nt][2], sacc[hf][nt][3]));
            }
        float av[4];
        #pragma unroll
        for (int j = 0; j < 4; j++) {
            mx[j] = fmaxf(mx[j], __shfl_xor_sync(0xffffffffu, mx[j], 1));
            mx[j] = fmaxf(mx[j], __shfl_xor_sync(0xffffffffu, mx[j], 2));
            float mn = fmaxf(m[j], mx[j]);
            av[j] = ex2(m[j] - mn);
            m[j] = mn;
            l[j] *= av[j];
        }

        float sum[4] = {0.f, 0.f, 0.f, 0.f};
        #pragma unroll
        for (int hf = 0; hf < 2; hf++) {
            #pragma unroll
            for (int nt = 0; nt < 8; nt++) {
                float p00 = ex2(sacc[hf][nt][0] - m[hf * 2]);
                float p01 = ex2(sacc[hf][nt][1] - m[hf * 2]);
                float p10 = ex2(sacc[hf][nt][2] - m[hf * 2 + 1]);
                float p11 = ex2(sacc[hf][nt][3] - m[hf * 2 + 1]);
                sum[hf * 2]     += p00 + p01;
                sum[hf * 2 + 1] += p10 + p11;
                oacc[hf][nt][0] *= av[hf * 2];
                oacc[hf][nt][1] *= av[hf * 2];
                oacc[hf][nt][2] *= av[hf * 2 + 1];
                oacc[hf][nt][3] *= av[hf * 2 + 1];
                uint32_t baddr = Pwarp + (uint32_t)(hf * 2048)
                               + (uint32_t)((nt >> 1) * 512)
                               + (uint32_t)(lane << 4) + (uint32_t)((nt & 1) * 8);
                asm volatile("st.shared.b32 [%0], %1;"
                             :: "r"(baddr),     "r"(pack_h2(p01, p00)) : "memory");
                asm volatile("st.shared.b32 [%0], %1;"
                             :: "r"(baddr + 4), "r"(pack_h2(p11, p10)) : "memory");
            }
        }
        #pragma unroll
        for (int j = 0; j < 4; j++) {
            sum[j] += __shfl_xor_sync(0xffffffffu, sum[j], 1);
            sum[j] += __shfl_xor_sync(0xffffffffu, sum[j], 2);
            l[j] += sum[j];
        }

        #pragma unroll
        for (int ks = 0; ks < 4; ks++) {
            uint32_t pa0[4], pa1[4];
            uint32_t pb = Pwarp + (uint32_t)(ks * 512) + (uint32_t)(lane << 4);
            asm volatile("ld.shared.v4.b32 {%0,%1,%2,%3}, [%4];"
                         : "=r"(pa0[0]), "=r"(pa0[1]), "=r"(pa0[2]), "=r"(pa0[3])
                         : "r"(pb));
            asm volatile("ld.shared.v4.b32 {%0,%1,%2,%3}, [%4];"
                         : "=r"(pa1[0]), "=r"(pa1[1]), "=r"(pa1[2]), "=r"(pa1[3])
                         : "r"(pb + 2048u));
            #pragma unroll
            for (int nt = 0; nt < 8; nt++) {
                uint32_t vb[2];
                uint32_t off = (uint32_t)((nt * 4 + ks) << 8) + (lane << 3);
                asm volatile("ld.shared.v2.b32 {%0,%1}, [%2];"
                             : "=r"(vb[0]), "=r"(vb[1]) : "r"(VsB + off));
                mma_f16(oacc[0][nt], pa0, vb);
                mma_f16(oacc[1][nt], pa1, vb);
            }
        }
    }

    {
        const int rb = b * 8 + blockIdx.x;
        #pragma unroll
        for (int hf = 0; hf < 2; hf++) {
            float inv0 = 1.f / l[hf * 2], inv1 = 1.f / l[hf * 2 + 1];
            int mt = w * 2 + hf;
            #pragma unroll
            for (int nt = 0; nt < 8; nt++) {
                int chunk = h * 2 + (nt >> 2);
                int k16s  = (nt >> 1) & 1;
                uint32_t rg = (uint32_t)((nt & 1) * 2);
                uint32_t* o = g_af2 + ((size_t)rb * NCHUNK + chunk) * 2048
                            + (k16s * 8 + mt) * 128 + lane * 4 + rg;
                o[0] = pack_h2(oacc[hf][nt][1] * inv0, oacc[hf][nt][0] * inv0);
                o[1] = pack_h2(oacc[hf][nt][3] * inv1, oacc[hf][nt][2] * inv1);
            }
        }
    }
}

// ---------------------------------------------------------------------------
extern "C" void kernel_launch(void* const* d_in, const int* in_sizes, int n_in,
                              void* d_out, int out_size)
{
    const float* x      = (const float*)d_in[0];
    const float* w_qkv  = (const float*)d_in[1];
    const float* b_qkv  = (const float*)d_in[2];
    const float* w_proj = (const float*)d_in[3];
    const float* b_proj = (const float*)d_in[4];
    float* out = (float*)d_out;

    uint32_t *xf = nullptr, *af2 = nullptr, *wqf = nullptr, *wpf = nullptr;
    cudaGetSymbolAddress((void**)&xf,  g_xf);
    cudaGetSymbolAddress((void**)&af2, g_af2);
    cudaGetSymbolAddress((void**)&wqf, g_wqf);
    cudaGetSymbolAddress((void**)&wpf, g_wpf);

    const int gemm_smem = 49152;   // 3 stages x 16 KB; mode-1 staging 33.3 KB
    const int attn_smem = 40960;
    cudaFuncSetAttribute(gemm2,
                         cudaFuncAttributeMaxDynamicSharedMemorySize, gemm_smem);
    cudaFuncSetAttribute(attn_mma,
                         cudaFuncAttributeMaxDynamicSharedMemorySize, attn_smem);

    // 0) all input conversions in one concurrent launch
    conv_all<<<dim3(88, 8), 256>>>(x, w_qkv, w_proj);

    // 1) QKV projection -> Q/K/V attention-native fragments (smem-staged)
    gemm2<<<dim3(QKVN / 128, MROWS / 128), 128, gemm_smem>>>(
        xf, wqf, b_qkv, out /*unused*/, QKVN, 1);

    // 2) attention -> proj A-fragments
    attn_mma<<<dim3(SEQ / 128, BATCH * NHEADS), 128, attn_smem>>>();

    // 3) output projection
    gemm2<<<dim3(DIM / 128, MROWS / 128), 128, gemm_smem>>>(
        af2, wpf, b_proj, out, DIM, 0);
}